// round 10
// baseline (speedup 1.0000x reference)
#include <cuda_runtime.h>
#include <math.h>

// ============================================================================
// ExponentialConcordanceLoss, O(N): zero cross-CTA communication (except an
// 8-entry ticket reduce), fixed monotone bucket map, ALL tables in SMEM.
//
// loss = ( sum_{i,j: t[j]<t[i], e[j], finite both} exp(s[i]-s[j]) ) / max(cnt,1)
//   a[i]  = finite[i] ? exp(s[i]) : 0
//   b0[j] = (finite[j] && e[j]) ? exp(-s[j]) : 0
//   total = sum_i a[i] * ( prefB0[bucket(i)] + same-bucket strict compares )
//
// Each of 8 plain blocks redundantly processes ALL 8192 elements into its OWN
// shared memory (redundant parallel work beats serialized cross-CTA round
// trips — established R5..R9), then gathers only its own 1024 elements:
//   1. zero SMEM hist; load all preds/targets (L2-multicast after first
//      toucher); prep t/b0/event in registers.  --- __syncthreads ---
//   2. hist + FIXED-SLOT scatter together (pos = atomicAdd(s_cnt[bkt]);
//      s_rec[bkt*MAXPER+pos] = (t,b0); SMEM atomics). Buckets fuller than
//      MAXPER spill to a per-CTA global overflow list (exact, ~never used:
//      Poisson(4) P(>12) ~ 1e-4).  --- __syncthreads ---
//   3. local exclusive scan of 1024 buckets (1/thread, shuffle scan).
//   4. gather own element: prefix + <=MAXPER SMEM slot reads (+ overflow
//      scan if that bucket overflowed). Strict < excludes ties/self.
//   5. block reduce; ticket: LAST block sums 8 partials in fixed order
//      (deterministic), writes out, resets ticket.
// Bucket map is FIXED (scale=KB/10 clamped): monotone for any input, and
// same-bucket pairs are resolved exactly, so any distribution (out-of-range,
// ties, NaN/inf via fin mask) is exact; balance only affects speed.
// Counts int32 end-to-end (max 8192^2 < 2^31).
// ============================================================================

#define NMAX   8192
#define KB     1024
#define MAXPER 12
#define NCTAS  8
#define NT     1024
#define EPT    (NMAX / NT)            // 8

__device__ float4   g_ovf[NCTAS][NMAX];   // per-CTA overflow (t, b0, bkt, -)
__device__ float    g_blockSum[NCTAS];
__device__ int      g_blockCnt[NCTAS];
__device__ unsigned g_ticket;             // zero at load; reset by last block

// Dynamic SMEM:
//   s_rec  : KB*MAXPER float2 = 98304 B
//   s_cnt  : KB int           =  4096 B
//   s_hB0  : KB float         =  4096 B
//   s_pB0  : KB float         =  4096 B
//   s_pC   : KB int           =  4096 B
#define SMEM_BYTES (KB * MAXPER * 8 + KB * 4 * 4)     // 114688

extern __shared__ unsigned char smem_raw[];

__global__ void __launch_bounds__(NT, 1)
fused6(const float* __restrict__ preds,
       const float* __restrict__ targets,
       float* __restrict__ out, int n) {
    float2* s_rec = (float2*)smem_raw;
    int*    s_cnt = (int*)(s_rec + KB * MAXPER);
    float*  s_hB0 = (float*)(s_cnt + KB);
    float*  s_pB0 = (float*)(s_hB0 + KB);
    int*    s_pC  = (int*)(s_pB0 + KB);

    __shared__ float sWsum[32];
    __shared__ int   sWcnt[32];
    __shared__ float sScanB[33];
    __shared__ int   sScanN[33];
    __shared__ int   sOvf;                 // per-CTA overflow count
    __shared__ int   sLast;

    const int tid  = threadIdx.x;
    const int cta  = blockIdx.x;
    const int lane = tid & 31;
    const int warp = tid >> 5;

    // ---- Phase 1: zero hist; load + prep all elements ----------------------
    s_cnt[tid] = 0;                         // KB == NT: 1 bucket / thread
    s_hB0[tid] = 0.0f;
    if (tid == 0) sOvf = 0;

    float tArr[EPT], b0Arr[EPT];
    int   eMask = 0;
    float my_s = 0.0f, my_t = 0.0f;
    bool  my_fin = false;
#pragma unroll
    for (int u = 0; u < EPT; u++) {
        int idx = u * NT + tid;
        float  sv = 0.0f;
        float2 tg = make_float2(__int_as_float(0x7fc00000), 0.0f);  // qNaN
        if (idx < n) {
            sv = __ldg(&preds[idx]);
            tg = __ldg(&((const float2*)targets)[idx]);
        }
        bool fin = isfinite(tg.x) && isfinite(sv);
        bool e   = fin && (tg.y != 0.0f);
        tArr[u]  = tg.x;
        b0Arr[u] = e ? __expf(-sv) : 0.0f;
        if (e) eMask |= (1 << u);
        if (u == cta) { my_s = sv; my_t = tg.x; my_fin = fin; }
    }
    __syncthreads();                        // hist zero visible

    // ---- Phase 2: hist + fixed-slot scatter (SMEM atomics) ------------------
    int my_bkt = 0;
#pragma unroll
    for (int u = 0; u < EPT; u++) {
        float x = tArr[u] * ((float)KB / 10.0f);   // fixed monotone map
        int b = (int)x;                            // NaN -> 0 after cvt
        b = max(0, min(KB - 1, b));
        if (u == cta) my_bkt = b;
        if (eMask & (1 << u)) {
            int pos = atomicAdd(&s_cnt[b], 1);
            atomicAdd(&s_hB0[b], b0Arr[u]);
            if (pos < MAXPER) {
                s_rec[b * MAXPER + pos] = make_float2(tArr[u], b0Arr[u]);
            } else {
                int o = atomicAdd(&sOvf, 1);
                g_ovf[cta][o] = make_float4(tArr[u], b0Arr[u],
                                            __int_as_float(b), 0.0f);
            }
        }
    }
    __syncthreads();

    // ---- Phase 3: local exclusive scan (1 bucket / thread) ------------------
    {
        float hb = s_hB0[tid];
        int   hn = s_cnt[tid];
        float rb = hb; int rn = hn;
#pragma unroll
        for (int o = 1; o < 32; o <<= 1) {
            float vb = __shfl_up_sync(0xffffffffu, rb, o);
            int   vn = __shfl_up_sync(0xffffffffu, rn, o);
            if (lane >= o) { rb += vb; rn += vn; }
        }
        if (lane == 31) { sScanB[warp] = rb; sScanN[warp] = rn; }
        __syncthreads();
        if (warp == 0) {
            float wb = sScanB[lane]; int wn = sScanN[lane];
#pragma unroll
            for (int o = 1; o < 32; o <<= 1) {
                float vb = __shfl_up_sync(0xffffffffu, wb, o);
                int   vn = __shfl_up_sync(0xffffffffu, wn, o);
                if (lane >= o) { wb += vb; wn += vn; }
            }
            sScanB[lane + 1] = wb; sScanN[lane + 1] = wn;
            if (lane == 0) { sScanB[0] = 0.0f; sScanN[0] = 0; }
        }
        __syncthreads();
        s_pB0[tid] = sScanB[warp] + rb - hb;       // exclusive
        s_pC[tid]  = sScanN[warp] + rn - hn;
    }
    __syncthreads();

    // ---- Phase 4: gather own element from SMEM ------------------------------
    float ts = 0.0f;
    int   tc = 0;
    if (my_fin) {
        float S   = s_pB0[my_bkt];
        int   C   = s_pC[my_bkt];
        int   cnt = s_cnt[my_bkt];
        int   lim = min(cnt, MAXPER);
        const float2* slot = &s_rec[my_bkt * MAXPER];
        for (int m = 0; m < lim; m++) {
            float2 r = slot[m];
            if (r.x < my_t) { S += r.y; C += 1; }  // strict: drops ties/self
        }
        if (cnt > MAXPER) {                        // rare exact path
            int on = sOvf;
            for (int o = 0; o < on; o++) {
                float4 r4 = g_ovf[cta][o];
                if (__float_as_int(r4.z) == my_bkt && r4.x < my_t) {
                    S += r4.y; C += 1;
                }
            }
        }
        ts = __expf(my_s) * S;
        tc = C;
    }

    // ---- Phase 5: block reduce + ticket final reduce ------------------------
#pragma unroll
    for (int o = 16; o > 0; o >>= 1) {
        ts += __shfl_xor_sync(0xffffffffu, ts, o);
        tc += __shfl_xor_sync(0xffffffffu, tc, o);
    }
    if (lane == 0) { sWsum[warp] = ts; sWcnt[warp] = tc; }
    __syncthreads();
    if (warp == 0) {
        float s2 = sWsum[lane];
        int   c2 = sWcnt[lane];
#pragma unroll
        for (int o = 16; o > 0; o >>= 1) {
            s2 += __shfl_xor_sync(0xffffffffu, s2, o);
            c2 += __shfl_xor_sync(0xffffffffu, c2, o);
        }
        if (lane == 0) { g_blockSum[cta] = s2; g_blockCnt[cta] = c2; }
    }
    __syncthreads();

    if (tid == 0) {
        __threadfence();
        unsigned tkt = atomicAdd(&g_ticket, 1u);
        sLast = (tkt == NCTAS - 1) ? 1 : 0;
        if (sLast) {
            __threadfence();
            float     s3 = 0.0f;
            long long c3 = 0;
#pragma unroll
            for (int b = 0; b < NCTAS; b++) {
                s3 += __ldcg(&g_blockSum[b]);
                c3 += (long long)__ldcg(&g_blockCnt[b]);
            }
            out[0] = s3 / fmaxf((float)c3, 1.0f);
            __threadfence();
            atomicExch(&g_ticket, 0u);             // reset for next replay
        }
    }
}

// ---------------------------------------------------------------------------
extern "C" void kernel_launch(void* const* d_in, const int* in_sizes, int n_in,
                              void* d_out, int out_size) {
    const float* preds   = (const float*)d_in[0];
    const float* targets = (const float*)d_in[1];
    int n = in_sizes[0];
    if (n > NMAX) n = NMAX;

    // Idempotent; needed for >48KB dynamic smem. Safe under graph capture.
    cudaFuncSetAttribute(fused6, cudaFuncAttributeMaxDynamicSharedMemorySize,
                         SMEM_BYTES);

    fused6<<<NCTAS, NT, SMEM_BYTES>>>(preds, targets, (float*)d_out, n);
}

// round 11
// speedup vs baseline: 1.0022x; 1.0022x over previous
#include <cuda_runtime.h>
#include <math.h>

// ============================================================================
// ExponentialConcordanceLoss, O(N), 8-CTA cluster, ONE cluster sync,
// fixed monotone bucket map, gather overlapped with the scan.
//
// loss = ( sum_{i,j: t[j]<t[i], e[j], finite both} exp(s[i]-s[j]) ) / max(cnt,1)
//   a[i]  = finite[i] ? exp(s[i]) : 0
//   b0[j] = (finite[j] && e[j]) ? exp(-s[j]) : 0
//   total = sum_i a[i] * ( prefB0[bucket(i)] + same-bucket strict compares )
//
// Structure (one launch, graph-replayable):
//   A: load own element; classify; b0=exp(-s); bkt = clamp(t*KB/10) (fixed
//      monotone map -- exact for ANY distribution because same-bucket pairs
//      are resolved against the original t with strict <; range only affects
//      balance). If event: pos=atomicAdd(g_cnt[bkt]); atomicAdd(g_hB0[bkt]);
//      record (t,b0) -> fixed slot g_srec2[bkt*MAXPER+pos] (one 128B line per
//      bucket), overflow list if bucket over-full (P ~ 1e-9 here, exact always).
//   --- cluster.sync (the only one) ---
//   B: IMMEDIATELY issue cnt[my_bkt] + 4x ld.v4 blind loads of the first 8
//      slot records; these fly while the per-CTA exclusive scan of 2048
//      buckets (2/thread, shuffle scan) runs. After the scan: local strict
//      compares on the preloaded records (+ remainder slots + overflow, both
//      rare), then S = prefix + local.
//   C: block reduce; ticket: LAST block re-zeroes hist for the next replay,
//      reduces the 8 partials in fixed order (deterministic), writes out.
// Counts int32 end-to-end (max 8192^2 < 2^31).
// ============================================================================

#define NMAX   8192
#define KB     2048
#define MAXPER 16
#define NCTAS  8
#define NT     1024

__device__ int      g_cnt[KB];            // zero at load; re-zeroed each run
__device__ float    g_hB0[KB];
__device__ float2   g_srec2[KB * MAXPER]; // fixed-slot records (stale ok)
__device__ float4   g_ovf[NMAX];          // overflow records (t, b0, bkt, -)
__device__ int      g_ovfCnt;
__device__ float    g_blockSum[NCTAS];
__device__ int      g_blockCnt[NCTAS];
__device__ unsigned g_ticket;             // zero at load; reset by last block

__device__ __forceinline__ void cluster_sync_fenced() {
    __threadfence();
    asm volatile("barrier.cluster.arrive.aligned;" ::: "memory");
    asm volatile("barrier.cluster.wait.aligned;"   ::: "memory");
}

__device__ __forceinline__ float4 ldcg_v4(const float4* p) {
    float4 v;
    asm volatile("ld.global.cg.v4.f32 {%0,%1,%2,%3}, [%4];"
                 : "=f"(v.x), "=f"(v.y), "=f"(v.z), "=f"(v.w) : "l"(p));
    return v;
}

__global__ void __launch_bounds__(NT, 1) __cluster_dims__(NCTAS, 1, 1)
fused7(const float* __restrict__ preds,
       const float* __restrict__ targets,
       float* __restrict__ out, int n) {
    __shared__ float sWsum[32];
    __shared__ int   sWcnt[32];
    __shared__ float sScanB[33];
    __shared__ int   sScanN[33];
    __shared__ float s_pB0[KB];           // exclusive prefix of event b0
    __shared__ int   s_pC[KB];            // exclusive prefix of event counts
    __shared__ int   sLast;

    const int tid  = threadIdx.x;
    const int cta  = blockIdx.x;
    const int i    = cta * NT + tid;
    const int lane = tid & 31;
    const int warp = tid >> 5;

    // ---- Phase A: own element; prep; hist + fixed-slot scatter --------------
    float sv = 0.0f;
    float my_t  = __int_as_float(0x7fc00000);   // qNaN
    float my_ev = 0.0f;
    if (i < n) {
        sv = __ldg(&preds[i]);
        float2 tg = __ldg(&((const float2*)targets)[i]);
        my_t = tg.x; my_ev = tg.y;
    }
    bool fin = isfinite(my_t) && isfinite(sv);  // i>=n -> NaN -> false
    bool e   = fin && (my_ev != 0.0f);
    float b0 = e ? __expf(-sv) : 0.0f;

    int bkt = 0;
    if (fin) {
        float x = my_t * ((float)KB / 10.0f);   // fixed monotone map
        bkt = (int)x;
        bkt = max(0, min(KB - 1, bkt));
    }
    if (e) {
        int pos = atomicAdd(&g_cnt[bkt], 1);
        atomicAdd(&g_hB0[bkt], b0);
        if (pos < MAXPER) {
            g_srec2[bkt * MAXPER + pos] = make_float2(my_t, b0);
        } else {
            int o = atomicAdd(&g_ovfCnt, 1);
            g_ovf[o] = make_float4(my_t, b0, __int_as_float(bkt), 0.0f);
        }
    }
    cluster_sync_fenced();                                 // the ONLY sync

    // ---- Phase B1: blind-issue own-bucket loads (fly under the scan) --------
    int    myCnt = 0;
    float4 q0, q1, q2, q3;
    q0 = q1 = q2 = q3 = make_float4(0.f, 0.f, 0.f, 0.f);
    if (fin) {
        myCnt = __ldcg(&g_cnt[bkt]);
        const float4* slot4 = (const float4*)&g_srec2[bkt * MAXPER];
        q0 = ldcg_v4(slot4 + 0);            // records 0,1
        q1 = ldcg_v4(slot4 + 1);            // records 2,3
        q2 = ldcg_v4(slot4 + 2);            // records 4,5
        q3 = ldcg_v4(slot4 + 3);            // records 6,7
    }

    // ---- Phase B2: per-CTA local exclusive scan (2 buckets / thread) --------
    {
        int   base = tid * 2;
        int   hn0 = __ldcg(&g_cnt[base]),  hn1 = __ldcg(&g_cnt[base + 1]);
        float hb0 = __ldcg(&g_hB0[base]),  hb1 = __ldcg(&g_hB0[base + 1]);

        float rb = hb0 + hb1;  int rn = hn0 + hn1;
        float Tb = rb;         int Tn = rn;
#pragma unroll
        for (int o = 1; o < 32; o <<= 1) {
            float vb = __shfl_up_sync(0xffffffffu, rb, o);
            int   vn = __shfl_up_sync(0xffffffffu, rn, o);
            if (lane >= o) { rb += vb; rn += vn; }
        }
        if (lane == 31) { sScanB[warp] = rb; sScanN[warp] = rn; }
        __syncthreads();
        if (warp == 0) {
            float wb = sScanB[lane]; int wn = sScanN[lane];
#pragma unroll
            for (int o = 1; o < 32; o <<= 1) {
                float vb = __shfl_up_sync(0xffffffffu, wb, o);
                int   vn = __shfl_up_sync(0xffffffffu, wn, o);
                if (lane >= o) { wb += vb; wn += vn; }
            }
            sScanB[lane + 1] = wb; sScanN[lane + 1] = wn;
            if (lane == 0) { sScanB[0] = 0.0f; sScanN[0] = 0; }
        }
        __syncthreads();
        float eb = sScanB[warp] + rb - Tb;                 // thread-exclusive
        int   ec = sScanN[warp] + rn - Tn;
        s_pB0[base]     = eb;        s_pB0[base + 1] = eb + hb0;
        s_pC[base]      = ec;        s_pC[base + 1]  = ec + hn0;
    }
    __syncthreads();

    // ---- Phase B3: local compares on preloaded records + prefix add ---------
    float ts = 0.0f;
    int   tc = 0;
    if (fin) {
        float S = 0.0f;
        int   C = 0;
        int lim = min(myCnt, 8);
        if (0 < lim && q0.x < my_t) { S += q0.y; C++; }
        if (1 < lim && q0.z < my_t) { S += q0.w; C++; }
        if (2 < lim && q1.x < my_t) { S += q1.y; C++; }
        if (3 < lim && q1.z < my_t) { S += q1.w; C++; }
        if (4 < lim && q2.x < my_t) { S += q2.y; C++; }
        if (5 < lim && q2.z < my_t) { S += q2.w; C++; }
        if (6 < lim && q3.x < my_t) { S += q3.y; C++; }
        if (7 < lim && q3.z < my_t) { S += q3.w; C++; }
        if (myCnt > 8) {                               // rare (P ~ 2e-4)
            int hi = min(myCnt, MAXPER);
            const float2* slot = &g_srec2[bkt * MAXPER];
            for (int m = 8; m < hi; m++) {
                float2 r;
                asm volatile("ld.global.cg.v2.f32 {%0,%1}, [%2];"
                             : "=f"(r.x), "=f"(r.y) : "l"(slot + m));
                if (r.x < my_t) { S += r.y; C++; }
            }
            if (myCnt > MAXPER) {                      // rarer still; exact
                int on = __ldcg(&g_ovfCnt);
                for (int o = 0; o < on; o++) {
                    float4 r4 = ldcg_v4(&g_ovf[o]);
                    if (__float_as_int(r4.z) == bkt && r4.x < my_t) {
                        S += r4.y; C++;
                    }
                }
            }
        }
        S += s_pB0[bkt];                               // strict-lower buckets
        C += s_pC[bkt];
        ts = __expf(sv) * S;
        tc = C;
    }

    // ---- Phase C: block reduce + ticket (last block zeroes + finalizes) -----
#pragma unroll
    for (int o = 16; o > 0; o >>= 1) {
        ts += __shfl_xor_sync(0xffffffffu, ts, o);
        tc += __shfl_xor_sync(0xffffffffu, tc, o);
    }
    if (lane == 0) { sWsum[warp] = ts; sWcnt[warp] = tc; }
    __syncthreads();
    if (warp == 0) {
        float s2 = sWsum[lane];
        int   c2 = sWcnt[lane];
#pragma unroll
        for (int o = 16; o > 0; o >>= 1) {
            s2 += __shfl_xor_sync(0xffffffffu, s2, o);
            c2 += __shfl_xor_sync(0xffffffffu, c2, o);
        }
        if (lane == 0) { g_blockSum[cta] = s2; g_blockCnt[cta] = c2; }
    }
    __syncthreads();

    if (tid == 0) {
        __threadfence();
        unsigned tkt = atomicAdd(&g_ticket, 1u);
        sLast = (tkt == NCTAS - 1) ? 1 : 0;
    }
    __syncthreads();
    if (sLast) {
        // all gathers done cluster-wide -> safe to re-zero for next replay
        g_cnt[tid]     = 0;     g_cnt[tid + NT] = 0;
        g_hB0[tid]     = 0.0f;  g_hB0[tid + NT] = 0.0f;
        if (tid == 0) {
            g_ovfCnt = 0;
            __threadfence();
            float     s3 = 0.0f;
            long long c3 = 0;
#pragma unroll
            for (int b = 0; b < NCTAS; b++) {
                s3 += __ldcg(&g_blockSum[b]);
                c3 += (long long)__ldcg(&g_blockCnt[b]);
            }
            out[0] = s3 / fmaxf((float)c3, 1.0f);
            __threadfence();
            atomicExch(&g_ticket, 0u);                 // reset for next replay
        }
    }
}

// ---------------------------------------------------------------------------
extern "C" void kernel_launch(void* const* d_in, const int* in_sizes, int n_in,
                              void* d_out, int out_size) {
    const float* preds   = (const float*)d_in[0];
    const float* targets = (const float*)d_in[1];
    int n = in_sizes[0];
    if (n > NMAX) n = NMAX;
    fused7<<<NCTAS, NT>>>(preds, targets, (float*)d_out, n);
}